// round 3
// baseline (speedup 1.0000x reference)
#include <cuda_runtime.h>

#define BATCH 16
#define H 256
#define W 256
#define HW (H*W)
#define NPLANE 12          // unique off-center taps (center weight == 1)
#define RAD 2
#define NITER 10

#define TW 32
#define TH 8
#define HALOW (TW + 2*RAD)   // 36
#define HALOH (TH + 2*RAD)   // 12

// Scratch (no cudaMalloc allowed): ~109 MB of __device__ globals.
// Weight planes total 100 MB -> fit in B200's 126 MB L2 across iterations.
__device__ float g_kA[BATCH * NPLANE * HW];   // feature kernel planes       (~50 MB)
__device__ float g_kB[BATCH * NPLANE * HW];   // feature*depth kernel planes (~50 MB)
__device__ float g_xA[2][BATCH * HW];         // chain A state (ping-pong)
__device__ float g_xB[2][BATCH * HW];         // chain B state (ping-pong)
__device__ unsigned int g_cnt[BATCH * 8];     // per batch: {inter,union} x 4 masks

// ---------------------------------------------------------------------------
// Init: x0 = clip(seg, 0.1, 0.9) for both chains; zero IoU counters.
// ---------------------------------------------------------------------------
__global__ __launch_bounds__(256) void mf_init(const float* __restrict__ seg) {
    int i = blockIdx.x * 256 + threadIdx.x;
    if (i < BATCH * HW) {
        float x = fminf(fmaxf(seg[i], 0.1f), 0.9f);
        g_xA[0][i] = x;
        g_xB[0][i] = x;
    }
    if (blockIdx.x == 0 && threadIdx.x < BATCH * 8)
        g_cnt[threadIdx.x] = 0u;
}

// ---------------------------------------------------------------------------
// Build the 12 unique-tap weight planes per batch (taps 0..11; mirror taps
// 24-t are shifted copies by symmetry, center tap is exactly 1).
// kernel  = exp(-sum_c (fm_n - fm_c)^2 / 0.02)  (fm = feature + 10; OOB -> 0)
// kernelD = kernel * exp(-(d_n - d_c)^2 / 0.02)
// Layout: g_k*[ ((b*12 + t) * HW) + hw ]  (coalesced over hw)
// ---------------------------------------------------------------------------
__global__ __launch_bounds__(256) void build_kernels(
    const float* __restrict__ fm, const float* __restrict__ depth) {
    __shared__ float sf0[HALOH][HALOW];
    __shared__ float sf1[HALOH][HALOW];
    __shared__ float sf2[HALOH][HALOW];
    __shared__ float sd [HALOH][HALOW];

    int b   = blockIdx.z;
    int ty0 = blockIdx.y * TH;
    int tx0 = blockIdx.x * TW;
    int tid = threadIdx.y * TW + threadIdx.x;

    for (int i = tid; i < HALOH * HALOW; i += TH * TW) {
        int hy = i / HALOW, hx = i % HALOW;
        int gy = ty0 + hy - RAD, gx = tx0 + hx - RAD;
        float f0 = 0.f, f1 = 0.f, f2 = 0.f, d = 0.f;
        if (gy >= 0 && gy < H && gx >= 0 && gx < W) {
            int idx = gy * W + gx;
            f0 = fm[(b * 3 + 0) * HW + idx] + 10.f;
            f1 = fm[(b * 3 + 1) * HW + idx] + 10.f;
            f2 = fm[(b * 3 + 2) * HW + idx] + 10.f;
            d  = depth[b * HW + idx];
        }
        sf0[hy][hx] = f0; sf1[hy][hx] = f1; sf2[hy][hx] = f2; sd[hy][hx] = d;
    }
    __syncthreads();

    int ly = threadIdx.y, lx = threadIdx.x;
    int gy = ty0 + ly, gx = tx0 + lx;
    int hw = gy * W + gx;

    float c0 = sf0[ly + RAD][lx + RAD];
    float c1 = sf1[ly + RAD][lx + RAD];
    float c2 = sf2[ly + RAD][lx + RAD];
    float cd = sd [ly + RAD][lx + RAD];

    float* kA = g_kA + (b * NPLANE) * HW + hw;
    float* kB = g_kB + (b * NPLANE) * HW + hw;

    #pragma unroll
    for (int t = 0; t < NPLANE; t++) {
        int kh = t / 5, kw = t % 5;
        float d0 = sf0[ly + kh][lx + kw] - c0;
        float d1 = sf1[ly + kh][lx + kw] - c1;
        float d2 = sf2[ly + kh][lx + kw] - c2;
        float s  = d0 * d0 + d1 * d1 + d2 * d2;
        float k  = expf(-(s / 0.02f));
        float dd = sd[ly + kh][lx + kw] - cd;
        float ks = k * expf(-((dd * dd) / 0.02f));
        kA[t * HW] = k;
        kB[t * HW] = ks;
    }
}

// ---------------------------------------------------------------------------
// One mean-field iteration, both chains fused, symmetric-tap formulation:
//   S(p) = L(p)  [center, w=1]
//        + sum_{t<12} P_t(p)      * L(p + o_t)   (tap t)
//        + sum_{t<12} P_t(p - o_t)* L(p - o_t)   (mirror tap 24-t)
// P_t(p-o) read out-of-image is 0 (predicated load), matching zero-pad unfold.
// Full batch per launch: grid 4096 blocks (~3.5 waves), weights L2-resident.
// ---------------------------------------------------------------------------
__global__ __launch_bounds__(256) void mf_iter(int src) {
    __shared__ float sA1[HALOH][HALOW];  // log(x)     chain A
    __shared__ float sA0[HALOH][HALOW];  // log(1-x)   chain A
    __shared__ float sB1[HALOH][HALOW];
    __shared__ float sB0[HALOH][HALOW];

    int b   = blockIdx.z;
    int ty0 = blockIdx.y * TH;
    int tx0 = blockIdx.x * TW;
    int tid = threadIdx.y * TW + threadIdx.x;

    const float* xAs = g_xA[src];
    const float* xBs = g_xB[src];
    float*       xAd = g_xA[src ^ 1];
    float*       xBd = g_xB[src ^ 1];

    for (int i = tid; i < HALOH * HALOW; i += TH * TW) {
        int hy = i / HALOW, hx = i % HALOW;
        int gy = ty0 + hy - RAD, gx = tx0 + hx - RAD;
        float a1 = 0.f, a0 = 0.f, b1 = 0.f, b0_ = 0.f;
        if (gy >= 0 && gy < H && gx >= 0 && gx < W) {
            int idx = b * HW + gy * W + gx;
            float xa = xAs[idx];
            float xb = xBs[idx];
            a1 = logf(xa); a0 = logf(1.0f - xa);
            b1 = logf(xb); b0_ = logf(1.0f - xb);
        }
        sA1[hy][hx] = a1; sA0[hy][hx] = a0;
        sB1[hy][hx] = b1; sB0[hy][hx] = b0_;
    }
    __syncthreads();

    int ly = threadIdx.y, lx = threadIdx.x;
    int gy = ty0 + ly, gx = tx0 + lx;
    int hw = gy * W + gx;

    const float* kA = g_kA + (b * NPLANE) * HW + hw;
    const float* kB = g_kB + (b * NPLANE) * HW + hw;

    float S1A = 0.f, S0A = 0.f, S1B = 0.f, S0B = 0.f;
    #pragma unroll
    for (int t = 0; t < NPLANE; t++) {
        const int kh = t / 5, kw = t % 5;
        const int off = (kh - RAD) * W + (kw - RAD);   // o_t flattened (negative)
        float wAf = __ldg(kA + t * HW);
        float wBf = __ldg(kB + t * HW);
        int byy = gy + RAD - kh;                       // p - o_t
        int bxx = gx + RAD - kw;
        bool ok = ((unsigned)byy < H) & ((unsigned)bxx < W);
        float wAb = ok ? __ldg(kA + t * HW - off) : 0.f;
        float wBb = ok ? __ldg(kB + t * HW - off) : 0.f;

        float f1A = sA1[ly + kh][lx + kw], f0A = sA0[ly + kh][lx + kw];
        float f1B = sB1[ly + kh][lx + kw], f0B = sB0[ly + kh][lx + kw];
        float m1A = sA1[ly + 4 - kh][lx + 4 - kw], m0A = sA0[ly + 4 - kh][lx + 4 - kw];
        float m1B = sB1[ly + 4 - kh][lx + 4 - kw], m0B = sB0[ly + 4 - kh][lx + 4 - kw];

        S1A += wAf * f1A + wAb * m1A;
        S0A += wAf * f0A + wAb * m0A;
        S1B += wBf * f1B + wBb * m1B;
        S0B += wBf * f0B + wBb * m0B;
    }
    // center tap: weight exactly exp(0) = 1 for both chains
    S1A += sA1[ly + RAD][lx + RAD];
    S0A += sA0[ly + RAD][lx + RAD];
    S1B += sB1[ly + RAD][lx + RAD];
    S0B += sB0[ly + RAD][lx + RAD];

    {
        float a1 = expf(S1A), a0 = expf(S0A);
        float x = a1 / (1e-6f + (a0 + a1));
        xAd[b * HW + hw] = fminf(fmaxf(x, 0.1f), 0.9f);
    }
    {
        float a1 = expf(S1B), a0 = expf(S0B);
        float x = a1 / (1e-6f + (a0 + a1));
        xBd[b * HW + hw] = fminf(fmaxf(x, 0.1f), 0.9f);
    }
}

// ---------------------------------------------------------------------------
// Finalize: write rgb_mask, accumulate per-batch inter/union for 4 masks.
// ---------------------------------------------------------------------------
__global__ __launch_bounds__(256) void finalize(
    const float* __restrict__ seg, const float* __restrict__ targets,
    const float* __restrict__ sam, int src, float* __restrict__ out_mask) {
    int b = blockIdx.y;
    int p = blockIdx.x * 256 + threadIdx.x;
    int i = b * HW + p;

    bool t  = (targets[i] != 0.f);
    bool m0 = (seg[i]       > 0.5f);
    bool m1 = (g_xA[src][i] > 0.5f);
    bool m2 = (g_xB[src][i] > 0.5f);
    bool m3 = (sam[i] != 0.f);

    out_mask[i] = m1 ? 1.f : 0.f;

    __shared__ unsigned int c[8];
    if (threadIdx.x < 8) c[threadIdx.x] = 0u;
    __syncthreads();

    bool preds[4] = {m0, m1, m2, m3};
    int lane = threadIdx.x & 31;
    #pragma unroll
    for (int m = 0; m < 4; m++) {
        unsigned bi = __ballot_sync(0xFFFFFFFFu, t && preds[m]);
        unsigned bu = __ballot_sync(0xFFFFFFFFu, t || preds[m]);
        if (lane == 0) {
            atomicAdd(&c[2 * m + 0], (unsigned)__popc(bi));
            atomicAdd(&c[2 * m + 1], (unsigned)__popc(bu));
        }
    }
    __syncthreads();
    if (threadIdx.x < 8)
        atomicAdd(&g_cnt[b * 8 + threadIdx.x], c[threadIdx.x]);
}

__global__ void iou_kernel(float* __restrict__ out_ious) {
    int m = threadIdx.x;
    if (m < 4) {
        float s = 0.f;
        for (int b = 0; b < BATCH; b++) {
            float inter = (float)g_cnt[b * 8 + 2 * m + 0];
            float uni   = (float)g_cnt[b * 8 + 2 * m + 1];
            s += inter / (uni + 1e-6f);
        }
        out_ious[m] = s * (1.0f / (float)BATCH);
    }
}

// ---------------------------------------------------------------------------
extern "C" void kernel_launch(void* const* d_in, const int* in_sizes, int n_in,
                              void* d_out, int out_size) {
    const float* fm      = (const float*)d_in[0];  // (16,3,256,256)
    const float* seg     = (const float*)d_in[1];  // (16,256,256)
    const float* depth   = (const float*)d_in[2];
    const float* targets = (const float*)d_in[3];
    const float* sam     = (const float*)d_in[4];
    float* out = (float*)d_out;

    dim3 blk(TW, TH);
    dim3 grd(W / TW, H / TH, BATCH);

    mf_init<<<(BATCH * HW + 255) / 256, 256>>>(seg);
    build_kernels<<<grd, blk>>>(fm, depth);

    // Full-batch iterations: 100 MB of weight planes stay L2-resident
    // (126 MB L2), so iterations 2..10 read weights from L2, not DRAM.
    int src = 0;
    for (int it = 0; it < NITER; it++) {
        mf_iter<<<grd, blk>>>(src);
        src ^= 1;
    }

    // after an even number of iterations, final state is in buffer 0
    finalize<<<dim3(HW / 256, BATCH), 256>>>(seg, targets, sam, 0, out);
    iou_kernel<<<1, 32>>>(out + (out_size - 4));
}

// round 4
// speedup vs baseline: 1.2105x; 1.2105x over previous
#include <cuda_runtime.h>

#define BATCH 16
#define H 256
#define W 256
#define HW (H*W)
#define NPLANE 12            // unique off-center taps (center weight == 1)
#define RAD 2
#define NITER 10

// padded weight plane: 2 cols left, 2 cols right, 2 rows bottom (zeros)
#define PW 260
#define PH 258
#define PLANE (PW*PH)

// mf_iter tile: 32x8 threads, 2 px/thread horizontally -> 64x8 pixels
#define TW 32
#define TH 8
#define TILEW 64
#define SHW (TILEW + 2*RAD)   // 68
#define SHH (TH + 2*RAD)      // 12

// build tile: 32x8 px
#define BHALOW (TW + 2*RAD)   // 36
#define BHALOH (TH + 2*RAD)   // 12

// Scratch (no cudaMalloc): ~145 MB of __device__ globals.
__device__ float2 g_k[BATCH * NPLANE * PLANE];  // interleaved {kA,kB}, padded (~103 MB)
__device__ float2 g_LA[2][BATCH * HW];          // chain A {log x, log(1-x)} ping-pong
__device__ float2 g_LB[2][BATCH * HW];          // chain B
__device__ float2 g_xfin[BATCH * HW];           // final {xA, xB}
__device__ unsigned int g_cnt[BATCH * 8];

// ---------------------------------------------------------------------------
__global__ __launch_bounds__(256) void mf_init(const float* __restrict__ seg) {
    int i = blockIdx.x * 256 + threadIdx.x;
    if (i < BATCH * HW) {
        float x = fminf(fmaxf(seg[i], 0.1f), 0.9f);
        float2 L = make_float2(logf(x), logf(1.0f - x));
        g_LA[0][i] = L;
        g_LB[0][i] = L;
    }
    if (blockIdx.x == 0 && threadIdx.x < BATCH * 8)
        g_cnt[threadIdx.x] = 0u;
}

// Zero the padding borders of every weight plane (interior written by build).
__global__ __launch_bounds__(256) void zero_pad() {
    float2* p = g_k + (size_t)blockIdx.x * PLANE;
    const float2 z = make_float2(0.f, 0.f);
    // bottom 2 rows, all cols
    for (int i = threadIdx.x; i < 2 * PW; i += 256) {
        int r = 256 + i / PW, c = i % PW;
        p[r * PW + c] = z;
    }
    // side cols 0,1,258,259 for rows 0..255
    for (int i = threadIdx.x; i < 256 * 4; i += 256) {
        int r = i / 4, cc = i % 4;
        int c = (cc < 2) ? cc : (256 + cc);
        p[r * PW + c] = z;
    }
}

// ---------------------------------------------------------------------------
// Build 12 unique-tap weight plane pairs per batch (mirror taps come from
// shifted reads of these planes; center tap weight is exactly 1).
// ---------------------------------------------------------------------------
__global__ __launch_bounds__(256) void build_kernels(
    const float* __restrict__ fm, const float* __restrict__ depth) {
    __shared__ float sf0[BHALOH][BHALOW];
    __shared__ float sf1[BHALOH][BHALOW];
    __shared__ float sf2[BHALOH][BHALOW];
    __shared__ float sd [BHALOH][BHALOW];

    int b   = blockIdx.z;
    int ty0 = blockIdx.y * TH;
    int tx0 = blockIdx.x * TW;
    int tid = threadIdx.y * TW + threadIdx.x;

    for (int i = tid; i < BHALOH * BHALOW; i += TH * TW) {
        int hy = i / BHALOW, hx = i % BHALOW;
        int gy = ty0 + hy - RAD, gx = tx0 + hx - RAD;
        float f0 = 0.f, f1 = 0.f, f2 = 0.f, d = 0.f;
        if (gy >= 0 && gy < H && gx >= 0 && gx < W) {
            int idx = gy * W + gx;
            f0 = fm[(b * 3 + 0) * HW + idx] + 10.f;
            f1 = fm[(b * 3 + 1) * HW + idx] + 10.f;
            f2 = fm[(b * 3 + 2) * HW + idx] + 10.f;
            d  = depth[b * HW + idx];
        }
        sf0[hy][hx] = f0; sf1[hy][hx] = f1; sf2[hy][hx] = f2; sd[hy][hx] = d;
    }
    __syncthreads();

    int ly = threadIdx.y, lx = threadIdx.x;
    int gy = ty0 + ly, gx = tx0 + lx;

    float c0 = sf0[ly + RAD][lx + RAD];
    float c1 = sf1[ly + RAD][lx + RAD];
    float c2 = sf2[ly + RAD][lx + RAD];
    float cd = sd [ly + RAD][lx + RAD];

    float2* kout = g_k + (size_t)(b * NPLANE) * PLANE + gy * PW + (gx + 2);

    #pragma unroll
    for (int t = 0; t < NPLANE; t++) {
        int kh = t / 5, kw = t % 5;
        float d0 = sf0[ly + kh][lx + kw] - c0;
        float d1 = sf1[ly + kh][lx + kw] - c1;
        float d2 = sf2[ly + kh][lx + kw] - c2;
        float s  = d0 * d0 + d1 * d1 + d2 * d2;
        float k  = expf(-(s / 0.02f));
        float dd = sd[ly + kh][lx + kw] - cd;
        float ks = k * expf(-((dd * dd) / 0.02f));
        kout[(size_t)t * PLANE] = make_float2(k, ks);
    }
}

// ---------------------------------------------------------------------------
// One mean-field iteration, both chains, 2 px/thread, symmetric taps:
//   S(p) = L(p) + sum_t [ w_t(p) * L(p+o_t) + w_t(p-o_t) * L(p-o_t) ]
// Weights read unconditionally from zero-padded planes.
// ---------------------------------------------------------------------------
__global__ __launch_bounds__(256) void mf_iter(int src, int last) {
    __shared__ float2 sA[SHH][SHW];   // {log x, log(1-x)} chain A
    __shared__ float2 sB[SHH][SHW];   // chain B

    int b   = blockIdx.z;
    int ty0 = blockIdx.y * TH;
    int tx0 = blockIdx.x * TILEW;
    int tid = threadIdx.y * TW + threadIdx.x;

    const float2* __restrict__ LAs = g_LA[src];
    const float2* __restrict__ LBs = g_LB[src];
    float2* LAd = g_LA[src ^ 1];
    float2* LBd = g_LB[src ^ 1];

    for (int i = tid; i < SHH * SHW; i += TH * TW) {
        int hy = i / SHW, hx = i % SHW;
        int gy = ty0 + hy - RAD, gx = tx0 + hx - RAD;
        float2 a = make_float2(0.f, 0.f), bb = make_float2(0.f, 0.f);
        if ((unsigned)gy < H && (unsigned)gx < W) {
            int idx = b * HW + gy * W + gx;
            a  = LAs[idx];
            bb = LBs[idx];
        }
        sA[hy][hx] = a; sB[hy][hx] = bb;
    }
    __syncthreads();

    int ly = threadIdx.y, lx = threadIdx.x;
    int x0 = 2 * lx;                 // tile-local col of px0
    int gy = ty0 + ly, gx0 = tx0 + x0;

    // weight pointer at (gy, gx0) of plane 0 for this batch
    const float2* __restrict__ kp =
        g_k + (size_t)(b * NPLANE) * PLANE + gy * PW + (gx0 + 2);

    float S1A0 = 0.f, S0A0 = 0.f, S1B0 = 0.f, S0B0 = 0.f;
    float S1A1 = 0.f, S0A1 = 0.f, S1B1 = 0.f, S0B1 = 0.f;

    #pragma unroll
    for (int t = 0; t < NPLANE; t++) {
        const int kh = t / 5, kw = t % 5;
        // forward weights for px0,px1: {A0,B0,A1,B1}
        float4 wf = *(const float4*)(kp + (size_t)t * PLANE);
        // mirror weights at p - o_t  (row gy+2-kh, col gx0+2-kw)
        const float2* mw = kp + (size_t)t * PLANE + (2 - kh) * PW + (2 - kw);
        float4 wm;
        if ((kw & 1) == 0) {
            wm = *(const float4*)mw;           // 16B aligned (kw even)
        } else {
            float2 m0 = mw[0], m1 = mw[1];
            wm = make_float4(m0.x, m0.y, m1.x, m1.y);
        }

        float2 fA0 = sA[ly + kh][x0 + kw],     fA1 = sA[ly + kh][x0 + kw + 1];
        float2 fB0 = sB[ly + kh][x0 + kw],     fB1 = sB[ly + kh][x0 + kw + 1];
        float2 mA0 = sA[ly + 4 - kh][x0 + 4 - kw], mA1 = sA[ly + 4 - kh][x0 + 5 - kw];
        float2 mB0 = sB[ly + 4 - kh][x0 + 4 - kw], mB1 = sB[ly + 4 - kh][x0 + 5 - kw];

        S1A0 += wf.x * fA0.x + wm.x * mA0.x;
        S0A0 += wf.x * fA0.y + wm.x * mA0.y;
        S1B0 += wf.y * fB0.x + wm.y * mB0.x;
        S0B0 += wf.y * fB0.y + wm.y * mB0.y;
        S1A1 += wf.z * fA1.x + wm.z * mA1.x;
        S0A1 += wf.z * fA1.y + wm.z * mA1.y;
        S1B1 += wf.w * fB1.x + wm.w * mB1.x;
        S0B1 += wf.w * fB1.y + wm.w * mB1.y;
    }
    // center tap: weight exactly 1
    {
        float2 cA0 = sA[ly + 2][x0 + 2], cA1 = sA[ly + 2][x0 + 3];
        float2 cB0 = sB[ly + 2][x0 + 2], cB1 = sB[ly + 2][x0 + 3];
        S1A0 += cA0.x; S0A0 += cA0.y; S1B0 += cB0.x; S0B0 += cB0.y;
        S1A1 += cA1.x; S0A1 += cA1.y; S1B1 += cB1.x; S0B1 += cB1.y;
    }

    int idx0 = b * HW + gy * W + gx0;

    float a1, a0;
    a1 = expf(S1A0); a0 = expf(S0A0);
    float xA0 = fminf(fmaxf(a1 / (1e-6f + (a0 + a1)), 0.1f), 0.9f);
    a1 = expf(S1B0); a0 = expf(S0B0);
    float xB0 = fminf(fmaxf(a1 / (1e-6f + (a0 + a1)), 0.1f), 0.9f);
    a1 = expf(S1A1); a0 = expf(S0A1);
    float xA1 = fminf(fmaxf(a1 / (1e-6f + (a0 + a1)), 0.1f), 0.9f);
    a1 = expf(S1B1); a0 = expf(S0B1);
    float xB1 = fminf(fmaxf(a1 / (1e-6f + (a0 + a1)), 0.1f), 0.9f);

    if (last) {
        g_xfin[idx0]     = make_float2(xA0, xB0);
        g_xfin[idx0 + 1] = make_float2(xA1, xB1);
    } else {
        LAd[idx0]     = make_float2(logf(xA0), logf(1.0f - xA0));
        LBd[idx0]     = make_float2(logf(xB0), logf(1.0f - xB0));
        LAd[idx0 + 1] = make_float2(logf(xA1), logf(1.0f - xA1));
        LBd[idx0 + 1] = make_float2(logf(xB1), logf(1.0f - xB1));
    }
}

// ---------------------------------------------------------------------------
__global__ __launch_bounds__(256) void finalize(
    const float* __restrict__ seg, const float* __restrict__ targets,
    const float* __restrict__ sam, float* __restrict__ out_mask) {
    int b = blockIdx.y;
    int p = blockIdx.x * 256 + threadIdx.x;
    int i = b * HW + p;

    float2 xf = g_xfin[i];
    bool t  = (targets[i] != 0.f);
    bool m0 = (seg[i] > 0.5f);
    bool m1 = (xf.x  > 0.5f);
    bool m2 = (xf.y  > 0.5f);
    bool m3 = (sam[i] != 0.f);

    out_mask[i] = m1 ? 1.f : 0.f;

    __shared__ unsigned int c[8];
    if (threadIdx.x < 8) c[threadIdx.x] = 0u;
    __syncthreads();

    bool preds[4] = {m0, m1, m2, m3};
    int lane = threadIdx.x & 31;
    #pragma unroll
    for (int m = 0; m < 4; m++) {
        unsigned bi = __ballot_sync(0xFFFFFFFFu, t && preds[m]);
        unsigned bu = __ballot_sync(0xFFFFFFFFu, t || preds[m]);
        if (lane == 0) {
            atomicAdd(&c[2 * m + 0], (unsigned)__popc(bi));
            atomicAdd(&c[2 * m + 1], (unsigned)__popc(bu));
        }
    }
    __syncthreads();
    if (threadIdx.x < 8)
        atomicAdd(&g_cnt[b * 8 + threadIdx.x], c[threadIdx.x]);
}

__global__ void iou_kernel(float* __restrict__ out_ious) {
    int m = threadIdx.x;
    if (m < 4) {
        float s = 0.f;
        for (int b = 0; b < BATCH; b++) {
            float inter = (float)g_cnt[b * 8 + 2 * m + 0];
            float uni   = (float)g_cnt[b * 8 + 2 * m + 1];
            s += inter / (uni + 1e-6f);
        }
        out_ious[m] = s * (1.0f / (float)BATCH);
    }
}

// ---------------------------------------------------------------------------
extern "C" void kernel_launch(void* const* d_in, const int* in_sizes, int n_in,
                              void* d_out, int out_size) {
    const float* fm      = (const float*)d_in[0];  // (16,3,256,256)
    const float* seg     = (const float*)d_in[1];  // (16,256,256)
    const float* depth   = (const float*)d_in[2];
    const float* targets = (const float*)d_in[3];
    const float* sam     = (const float*)d_in[4];
    float* out = (float*)d_out;

    mf_init<<<(BATCH * HW + 255) / 256, 256>>>(seg);
    zero_pad<<<BATCH * NPLANE, 256>>>();
    build_kernels<<<dim3(W / TW, H / TH, BATCH), dim3(TW, TH)>>>(fm, depth);

    dim3 blk(TW, TH);
    dim3 grd(W / TILEW, H / TH, BATCH);   // (4, 32, 16) = 2048 blocks
    int src = 0;
    for (int it = 0; it < NITER; it++) {
        mf_iter<<<grd, blk>>>(src, it == NITER - 1);
        src ^= 1;
    }

    finalize<<<dim3(HW / 256, BATCH), 256>>>(seg, targets, sam, out);
    iou_kernel<<<1, 32>>>(out + (out_size - 4));
}

// round 5
// speedup vs baseline: 1.2319x; 1.0177x over previous
#include <cuda_runtime.h>

#define BATCH 16
#define H 256
#define W 256
#define HW (H*W)
#define NPLANE 12            // unique off-center taps (center weight == 1)
#define RAD 2
#define NITER 10

// padded weight plane: 2 cols left, 2 cols right, 2 rows bottom (zeros)
#define PW 260
#define PH 258
#define PLANE (PW*PH)

// mf_iter tile: 32x8 threads, 2 px/thread (lx and lx+32) -> 64x8 pixels
#define TW 32
#define TH 8
#define TILEW 64
#define SHW (TILEW + 2*RAD)   // 68
#define SHH (TH + 2*RAD)      // 12

// build tile: 32x8 px
#define BHALOW (TW + 2*RAD)   // 36
#define BHALOH (TH + 2*RAD)   // 12

// Scratch (no cudaMalloc): ~137 MB of __device__ globals.
__device__ float2 g_k[BATCH * NPLANE * PLANE];  // interleaved {kA,kB}, padded (~103 MB)
__device__ float2 g_LA[2][BATCH * HW];          // chain A {log x, log(1-x)} ping-pong
__device__ float2 g_LB[2][BATCH * HW];          // chain B
__device__ unsigned int g_cnt[BATCH * 8];

// ---------------------------------------------------------------------------
__global__ __launch_bounds__(256) void mf_init(const float* __restrict__ seg) {
    int i = blockIdx.x * 256 + threadIdx.x;
    if (i < BATCH * HW) {
        float x = fminf(fmaxf(seg[i], 0.1f), 0.9f);
        float2 L = make_float2(logf(x), logf(1.0f - x));
        g_LA[0][i] = L;
        g_LB[0][i] = L;
    }
    if (blockIdx.x == 0 && threadIdx.x < BATCH * 8)
        g_cnt[threadIdx.x] = 0u;
}

// Zero the padding borders of every weight plane (interior written by build).
__global__ __launch_bounds__(256) void zero_pad() {
    float2* p = g_k + (size_t)blockIdx.x * PLANE;
    const float2 z = make_float2(0.f, 0.f);
    for (int i = threadIdx.x; i < 2 * PW; i += 256) {
        int r = 256 + i / PW, c = i % PW;
        p[r * PW + c] = z;
    }
    for (int i = threadIdx.x; i < 256 * 4; i += 256) {
        int r = i / 4, cc = i % 4;
        int c = (cc < 2) ? cc : (256 + cc);
        p[r * PW + c] = z;
    }
}

// ---------------------------------------------------------------------------
// Build 12 unique-tap weight plane pairs per batch (mirror taps come from
// shifted reads of these planes; center tap weight is exactly 1).
// ---------------------------------------------------------------------------
__global__ __launch_bounds__(256) void build_kernels(
    const float* __restrict__ fm, const float* __restrict__ depth) {
    __shared__ float sf0[BHALOH][BHALOW];
    __shared__ float sf1[BHALOH][BHALOW];
    __shared__ float sf2[BHALOH][BHALOW];
    __shared__ float sd [BHALOH][BHALOW];

    int b   = blockIdx.z;
    int ty0 = blockIdx.y * TH;
    int tx0 = blockIdx.x * TW;
    int tid = threadIdx.y * TW + threadIdx.x;

    for (int i = tid; i < BHALOH * BHALOW; i += TH * TW) {
        int hy = i / BHALOW, hx = i % BHALOW;
        int gy = ty0 + hy - RAD, gx = tx0 + hx - RAD;
        float f0 = 0.f, f1 = 0.f, f2 = 0.f, d = 0.f;
        if (gy >= 0 && gy < H && gx >= 0 && gx < W) {
            int idx = gy * W + gx;
            f0 = fm[(b * 3 + 0) * HW + idx] + 10.f;
            f1 = fm[(b * 3 + 1) * HW + idx] + 10.f;
            f2 = fm[(b * 3 + 2) * HW + idx] + 10.f;
            d  = depth[b * HW + idx];
        }
        sf0[hy][hx] = f0; sf1[hy][hx] = f1; sf2[hy][hx] = f2; sd[hy][hx] = d;
    }
    __syncthreads();

    int ly = threadIdx.y, lx = threadIdx.x;
    int gy = ty0 + ly, gx = tx0 + lx;

    float c0 = sf0[ly + RAD][lx + RAD];
    float c1 = sf1[ly + RAD][lx + RAD];
    float c2 = sf2[ly + RAD][lx + RAD];
    float cd = sd [ly + RAD][lx + RAD];

    float2* kout = g_k + (size_t)(b * NPLANE) * PLANE + gy * PW + (gx + 2);

    #pragma unroll
    for (int t = 0; t < NPLANE; t++) {
        int kh = t / 5, kw = t % 5;
        float d0 = sf0[ly + kh][lx + kw] - c0;
        float d1 = sf1[ly + kh][lx + kw] - c1;
        float d2 = sf2[ly + kh][lx + kw] - c2;
        float s  = d0 * d0 + d1 * d1 + d2 * d2;
        float k  = expf(-(s / 0.02f));
        float dd = sd[ly + kh][lx + kw] - cd;
        float ks = k * expf(-((dd * dd) / 0.02f));
        kout[(size_t)t * PLANE] = make_float2(k, ks);
    }
}

// ---------------------------------------------------------------------------
// One mean-field iteration, both chains, 2 px/thread (lx, lx+32):
//   S(p) = L(p) + sum_t [ w_t(p) * L(p+o_t) + w_t(p-o_t) * L(p-o_t) ]
// Weights read unconditionally from zero-padded planes (8B coalesced).
// All LDS are stride-1 float2 -> conflict-free.
// Last iteration fuses mask write + IoU counting.
// ---------------------------------------------------------------------------
__global__ __launch_bounds__(256, 5) void mf_iter(
    int src, int last,
    const float* __restrict__ seg, const float* __restrict__ targets,
    const float* __restrict__ sam, float* __restrict__ out_mask) {
    __shared__ float2 sA[SHH][SHW];   // {log x, log(1-x)} chain A
    __shared__ float2 sB[SHH][SHW];   // chain B

    int b   = blockIdx.z;
    int ty0 = blockIdx.y * TH;
    int tx0 = blockIdx.x * TILEW;
    int tid = threadIdx.y * TW + threadIdx.x;

    const float2* __restrict__ LAs = g_LA[src];
    const float2* __restrict__ LBs = g_LB[src];
    float2* LAd = g_LA[src ^ 1];
    float2* LBd = g_LB[src ^ 1];

    for (int i = tid; i < SHH * SHW; i += TH * TW) {
        int hy = i / SHW, hx = i % SHW;
        int gy = ty0 + hy - RAD, gx = tx0 + hx - RAD;
        float2 a = make_float2(0.f, 0.f), bb = make_float2(0.f, 0.f);
        if ((unsigned)gy < H && (unsigned)gx < W) {
            int idx = b * HW + gy * W + gx;
            a  = LAs[idx];
            bb = LBs[idx];
        }
        sA[hy][hx] = a; sB[hy][hx] = bb;
    }
    __syncthreads();

    int ly = threadIdx.y, lx = threadIdx.x;
    int gy = ty0 + ly, gx0 = tx0 + lx;       // px1 at gx0 + 32

    const float2* __restrict__ kp =
        g_k + (size_t)(b * NPLANE) * PLANE + gy * PW + (gx0 + 2);

    float S1A0 = 0.f, S0A0 = 0.f, S1B0 = 0.f, S0B0 = 0.f;
    float S1A1 = 0.f, S0A1 = 0.f, S1B1 = 0.f, S0B1 = 0.f;

    #pragma unroll
    for (int t = 0; t < NPLANE; t++) {
        const int kh = t / 5, kw = t % 5;
        const int moff = (2 - kh) * PW + (2 - kw);   // mirror weight offset
        float2 wf0 = __ldg(kp + (size_t)t * PLANE);
        float2 wf1 = __ldg(kp + (size_t)t * PLANE + 32);
        float2 wm0 = __ldg(kp + (size_t)t * PLANE + moff);
        float2 wm1 = __ldg(kp + (size_t)t * PLANE + moff + 32);

        float2 fA0 = sA[ly + kh][lx + kw];
        float2 fB0 = sB[ly + kh][lx + kw];
        float2 fA1 = sA[ly + kh][lx + kw + 32];
        float2 fB1 = sB[ly + kh][lx + kw + 32];
        float2 mA0 = sA[ly + 4 - kh][lx + 4 - kw];
        float2 mB0 = sB[ly + 4 - kh][lx + 4 - kw];
        float2 mA1 = sA[ly + 4 - kh][lx + 4 - kw + 32];
        float2 mB1 = sB[ly + 4 - kh][lx + 4 - kw + 32];

        S1A0 += wf0.x * fA0.x + wm0.x * mA0.x;
        S0A0 += wf0.x * fA0.y + wm0.x * mA0.y;
        S1B0 += wf0.y * fB0.x + wm0.y * mB0.x;
        S0B0 += wf0.y * fB0.y + wm0.y * mB0.y;
        S1A1 += wf1.x * fA1.x + wm1.x * mA1.x;
        S0A1 += wf1.x * fA1.y + wm1.x * mA1.y;
        S1B1 += wf1.y * fB1.x + wm1.y * mB1.x;
        S0B1 += wf1.y * fB1.y + wm1.y * mB1.y;
    }
    // center tap: weight exactly 1
    {
        float2 cA0 = sA[ly + 2][lx + 2], cA1 = sA[ly + 2][lx + 34];
        float2 cB0 = sB[ly + 2][lx + 2], cB1 = sB[ly + 2][lx + 34];
        S1A0 += cA0.x; S0A0 += cA0.y; S1B0 += cB0.x; S0B0 += cB0.y;
        S1A1 += cA1.x; S0A1 += cA1.y; S1B1 += cB1.x; S0B1 += cB1.y;
    }

    int idx0 = b * HW + gy * W + gx0;

    float a1, a0;
    a1 = expf(S1A0); a0 = expf(S0A0);
    float xA0 = fminf(fmaxf(a1 / (1e-6f + (a0 + a1)), 0.1f), 0.9f);
    a1 = expf(S1B0); a0 = expf(S0B0);
    float xB0 = fminf(fmaxf(a1 / (1e-6f + (a0 + a1)), 0.1f), 0.9f);
    a1 = expf(S1A1); a0 = expf(S0A1);
    float xA1 = fminf(fmaxf(a1 / (1e-6f + (a0 + a1)), 0.1f), 0.9f);
    a1 = expf(S1B1); a0 = expf(S0B1);
    float xB1 = fminf(fmaxf(a1 / (1e-6f + (a0 + a1)), 0.1f), 0.9f);

    if (!last) {
        LAd[idx0]      = make_float2(logf(xA0), logf(1.0f - xA0));
        LBd[idx0]      = make_float2(logf(xB0), logf(1.0f - xB0));
        LAd[idx0 + 32] = make_float2(logf(xA1), logf(1.0f - xA1));
        LBd[idx0 + 32] = make_float2(logf(xB1), logf(1.0f - xB1));
    } else {
        // fused finalize: rgb_mask write + per-batch IoU counting
        bool t0 = (targets[idx0]      != 0.f);
        bool t1 = (targets[idx0 + 32] != 0.f);
        bool p00 = (seg[idx0]       > 0.5f), p01 = (seg[idx0 + 32]  > 0.5f);
        bool p10 = (xA0 > 0.5f),             p11 = (xA1 > 0.5f);
        bool p20 = (xB0 > 0.5f),             p21 = (xB1 > 0.5f);
        bool p30 = (sam[idx0] != 0.f),       p31 = (sam[idx0 + 32] != 0.f);

        out_mask[idx0]      = p10 ? 1.f : 0.f;
        out_mask[idx0 + 32] = p11 ? 1.f : 0.f;

        __shared__ unsigned int c[8];
        if (tid < 8) c[tid] = 0u;
        __syncthreads();

        bool pr0[4] = {p00, p10, p20, p30};
        bool pr1[4] = {p01, p11, p21, p31};
        int lane = threadIdx.x;   // TW == 32, so threadIdx.x is the lane id
        #pragma unroll
        for (int m = 0; m < 4; m++) {
            unsigned bi = __ballot_sync(0xFFFFFFFFu, t0 && pr0[m]);
            unsigned bu = __ballot_sync(0xFFFFFFFFu, t0 || pr0[m]);
            unsigned ci = __ballot_sync(0xFFFFFFFFu, t1 && pr1[m]);
            unsigned cu = __ballot_sync(0xFFFFFFFFu, t1 || pr1[m]);
            if (lane == 0) {
                atomicAdd(&c[2 * m + 0], (unsigned)(__popc(bi) + __popc(ci)));
                atomicAdd(&c[2 * m + 1], (unsigned)(__popc(bu) + __popc(cu)));
            }
        }
        __syncthreads();
        if (tid < 8)
            atomicAdd(&g_cnt[b * 8 + tid], c[tid]);
    }
}

__global__ void iou_kernel(float* __restrict__ out_ious) {
    int m = threadIdx.x;
    if (m < 4) {
        float s = 0.f;
        for (int b = 0; b < BATCH; b++) {
            float inter = (float)g_cnt[b * 8 + 2 * m + 0];
            float uni   = (float)g_cnt[b * 8 + 2 * m + 1];
            s += inter / (uni + 1e-6f);
        }
        out_ious[m] = s * (1.0f / (float)BATCH);
    }
}

// ---------------------------------------------------------------------------
extern "C" void kernel_launch(void* const* d_in, const int* in_sizes, int n_in,
                              void* d_out, int out_size) {
    const float* fm      = (const float*)d_in[0];  // (16,3,256,256)
    const float* seg     = (const float*)d_in[1];  // (16,256,256)
    const float* depth   = (const float*)d_in[2];
    const float* targets = (const float*)d_in[3];
    const float* sam     = (const float*)d_in[4];
    float* out = (float*)d_out;

    mf_init<<<(BATCH * HW + 255) / 256, 256>>>(seg);
    zero_pad<<<BATCH * NPLANE, 256>>>();
    build_kernels<<<dim3(W / TW, H / TH, BATCH), dim3(TW, TH)>>>(fm, depth);

    dim3 blk(TW, TH);
    dim3 grd(W / TILEW, H / TH, BATCH);   // (4, 32, 16) = 2048 blocks
    int src = 0;
    for (int it = 0; it < NITER; it++) {
        mf_iter<<<grd, blk>>>(src, it == NITER - 1, seg, targets, sam, out);
        src ^= 1;
    }

    iou_kernel<<<1, 32>>>(out + (out_size - 4));
}

// round 6
// speedup vs baseline: 1.2618x; 1.0242x over previous
#include <cuda_runtime.h>

#define BATCH 16
#define H 256
#define W 256
#define HW (H*W)
#define NPLANE 12            // unique off-center taps (center weight == 1)
#define RAD 2
#define NITER 10

// padded weight plane: 2 cols left, 2 cols right, 2 rows bottom (zeros)
#define PW 260
#define PH 258
#define PLANE (PW*PH)

// mf_iter tile: 32x8 threads, 2 px/thread (lx and lx+32) -> 64x8 pixels
#define TW 32
#define TH 8
#define TILEW 64
#define SHW (TILEW + 2*RAD)   // 68
#define SHH (TH + 2*RAD)      // 12

// build tile: 32x8 px
#define BHALOW (TW + 2*RAD)   // 36
#define BHALOH (TH + 2*RAD)   // 12

// Scratch (no cudaMalloc): ~137 MB of __device__ globals.
__device__ float2 g_k[BATCH * NPLANE * PLANE];  // interleaved {kA,kB}, padded (~103 MB)
__device__ float4 g_L[2][BATCH * HW];           // {logxA, log1mxA, logxB, log1mxB} ping-pong
__device__ unsigned int g_cnt[BATCH * 8];

// ---------------------------------------------------------------------------
__global__ __launch_bounds__(256) void mf_init(const float* __restrict__ seg) {
    int i = blockIdx.x * 256 + threadIdx.x;
    if (i < BATCH * HW) {
        float x = fminf(fmaxf(seg[i], 0.1f), 0.9f);
        float l1 = logf(x), l0 = logf(1.0f - x);
        g_L[0][i] = make_float4(l1, l0, l1, l0);
    }
    if (blockIdx.x == 0 && threadIdx.x < BATCH * 8)
        g_cnt[threadIdx.x] = 0u;
}

// Zero the padding borders of every weight plane (interior written by build).
__global__ __launch_bounds__(256) void zero_pad() {
    float2* p = g_k + (size_t)blockIdx.x * PLANE;
    const float2 z = make_float2(0.f, 0.f);
    for (int i = threadIdx.x; i < 2 * PW; i += 256) {
        int r = 256 + i / PW, c = i % PW;
        p[r * PW + c] = z;
    }
    for (int i = threadIdx.x; i < 256 * 4; i += 256) {
        int r = i / 4, cc = i % 4;
        int c = (cc < 2) ? cc : (256 + cc);
        p[r * PW + c] = z;
    }
}

// ---------------------------------------------------------------------------
// Build 12 unique-tap weight plane pairs per batch (mirror taps come from
// shifted reads of these planes; center tap weight is exactly 1).
// ---------------------------------------------------------------------------
__global__ __launch_bounds__(256) void build_kernels(
    const float* __restrict__ fm, const float* __restrict__ depth) {
    __shared__ float sf0[BHALOH][BHALOW];
    __shared__ float sf1[BHALOH][BHALOW];
    __shared__ float sf2[BHALOH][BHALOW];
    __shared__ float sd [BHALOH][BHALOW];

    int b   = blockIdx.z;
    int ty0 = blockIdx.y * TH;
    int tx0 = blockIdx.x * TW;
    int tid = threadIdx.y * TW + threadIdx.x;

    for (int i = tid; i < BHALOH * BHALOW; i += TH * TW) {
        int hy = i / BHALOW, hx = i % BHALOW;
        int gy = ty0 + hy - RAD, gx = tx0 + hx - RAD;
        float f0 = 0.f, f1 = 0.f, f2 = 0.f, d = 0.f;
        if (gy >= 0 && gy < H && gx >= 0 && gx < W) {
            int idx = gy * W + gx;
            f0 = fm[(b * 3 + 0) * HW + idx] + 10.f;
            f1 = fm[(b * 3 + 1) * HW + idx] + 10.f;
            f2 = fm[(b * 3 + 2) * HW + idx] + 10.f;
            d  = depth[b * HW + idx];
        }
        sf0[hy][hx] = f0; sf1[hy][hx] = f1; sf2[hy][hx] = f2; sd[hy][hx] = d;
    }
    __syncthreads();

    int ly = threadIdx.y, lx = threadIdx.x;
    int gy = ty0 + ly, gx = tx0 + lx;

    float c0 = sf0[ly + RAD][lx + RAD];
    float c1 = sf1[ly + RAD][lx + RAD];
    float c2 = sf2[ly + RAD][lx + RAD];
    float cd = sd [ly + RAD][lx + RAD];

    float2* kout = g_k + (size_t)(b * NPLANE) * PLANE + gy * PW + (gx + 2);

    #pragma unroll
    for (int t = 0; t < NPLANE; t++) {
        int kh = t / 5, kw = t % 5;
        float d0 = sf0[ly + kh][lx + kw] - c0;
        float d1 = sf1[ly + kh][lx + kw] - c1;
        float d2 = sf2[ly + kh][lx + kw] - c2;
        float s  = d0 * d0 + d1 * d1 + d2 * d2;
        float k  = expf(-(s / 0.02f));
        float dd = sd[ly + kh][lx + kw] - cd;
        float ks = k * expf(-((dd * dd) / 0.02f));
        kout[(size_t)t * PLANE] = make_float2(k, ks);
    }
}

// ---------------------------------------------------------------------------
// One mean-field iteration, both chains packed in float4, 2 px/thread:
//   S(p) = L(p) + sum_t [ w_t(p) * L(p+o_t) + w_t(p-o_t) * L(p-o_t) ]
// Weights (default cache policy -> L2-resident across iterations) read
// unconditionally from zero-padded planes. L state uses streaming hints.
// Last iteration fuses mask write + IoU counting.
// ---------------------------------------------------------------------------
__global__ __launch_bounds__(256, 5) void mf_iter(
    int src, int last,
    const float* __restrict__ seg, const float* __restrict__ targets,
    const float* __restrict__ sam, float* __restrict__ out_mask) {
    __shared__ float4 sb[SHH][SHW];   // {logxA, log1mxA, logxB, log1mxB}

    int b   = blockIdx.z;
    int ty0 = blockIdx.y * TH;
    int tx0 = blockIdx.x * TILEW;
    int tid = threadIdx.y * TW + threadIdx.x;

    const float4* __restrict__ Ls = g_L[src];
    float4* Ld = g_L[src ^ 1];

    for (int i = tid; i < SHH * SHW; i += TH * TW) {
        int hy = i / SHW, hx = i % SHW;
        int gy = ty0 + hy - RAD, gx = tx0 + hx - RAD;
        float4 v = make_float4(0.f, 0.f, 0.f, 0.f);
        if ((unsigned)gy < H && (unsigned)gx < W)
            v = __ldcs(&Ls[b * HW + gy * W + gx]);
        sb[hy][hx] = v;
    }
    __syncthreads();

    int ly = threadIdx.y, lx = threadIdx.x;
    int gy = ty0 + ly, gx0 = tx0 + lx;       // px1 at gx0 + 32

    const float2* __restrict__ kp =
        g_k + (size_t)(b * NPLANE) * PLANE + gy * PW + (gx0 + 2);

    float S1A0 = 0.f, S0A0 = 0.f, S1B0 = 0.f, S0B0 = 0.f;
    float S1A1 = 0.f, S0A1 = 0.f, S1B1 = 0.f, S0B1 = 0.f;

    #pragma unroll
    for (int t = 0; t < NPLANE; t++) {
        const int kh = t / 5, kw = t % 5;
        const int moff = (2 - kh) * PW + (2 - kw);   // mirror weight offset
        float2 wf0 = __ldg(kp + (size_t)t * PLANE);
        float2 wf1 = __ldg(kp + (size_t)t * PLANE + 32);
        float2 wm0 = __ldg(kp + (size_t)t * PLANE + moff);
        float2 wm1 = __ldg(kp + (size_t)t * PLANE + moff + 32);

        float4 f0 = sb[ly + kh][lx + kw];
        float4 f1 = sb[ly + kh][lx + kw + 32];
        float4 m0 = sb[ly + 4 - kh][lx + 4 - kw];
        float4 m1 = sb[ly + 4 - kh][lx + 4 - kw + 32];

        S1A0 += wf0.x * f0.x + wm0.x * m0.x;
        S0A0 += wf0.x * f0.y + wm0.x * m0.y;
        S1B0 += wf0.y * f0.z + wm0.y * m0.z;
        S0B0 += wf0.y * f0.w + wm0.y * m0.w;
        S1A1 += wf1.x * f1.x + wm1.x * m1.x;
        S0A1 += wf1.x * f1.y + wm1.x * m1.y;
        S1B1 += wf1.y * f1.z + wm1.y * m1.z;
        S0B1 += wf1.y * f1.w + wm1.y * m1.w;
    }
    // center tap: weight exactly 1
    {
        float4 c0 = sb[ly + 2][lx + 2], c1 = sb[ly + 2][lx + 34];
        S1A0 += c0.x; S0A0 += c0.y; S1B0 += c0.z; S0B0 += c0.w;
        S1A1 += c1.x; S0A1 += c1.y; S1B1 += c1.z; S0B1 += c1.w;
    }

    int idx0 = b * HW + gy * W + gx0;

    float a1, a0;
    a1 = expf(S1A0); a0 = expf(S0A0);
    float xA0 = fminf(fmaxf(a1 / (1e-6f + (a0 + a1)), 0.1f), 0.9f);
    a1 = expf(S1B0); a0 = expf(S0B0);
    float xB0 = fminf(fmaxf(a1 / (1e-6f + (a0 + a1)), 0.1f), 0.9f);
    a1 = expf(S1A1); a0 = expf(S0A1);
    float xA1 = fminf(fmaxf(a1 / (1e-6f + (a0 + a1)), 0.1f), 0.9f);
    a1 = expf(S1B1); a0 = expf(S0B1);
    float xB1 = fminf(fmaxf(a1 / (1e-6f + (a0 + a1)), 0.1f), 0.9f);

    if (!last) {
        __stcs(&Ld[idx0], make_float4(logf(xA0), logf(1.0f - xA0),
                                      logf(xB0), logf(1.0f - xB0)));
        __stcs(&Ld[idx0 + 32], make_float4(logf(xA1), logf(1.0f - xA1),
                                           logf(xB1), logf(1.0f - xB1)));
    } else {
        // fused finalize: rgb_mask write + per-batch IoU counting
        bool t0 = (targets[idx0]      != 0.f);
        bool t1 = (targets[idx0 + 32] != 0.f);
        bool p00 = (seg[idx0]       > 0.5f), p01 = (seg[idx0 + 32]  > 0.5f);
        bool p10 = (xA0 > 0.5f),             p11 = (xA1 > 0.5f);
        bool p20 = (xB0 > 0.5f),             p21 = (xB1 > 0.5f);
        bool p30 = (sam[idx0] != 0.f),       p31 = (sam[idx0 + 32] != 0.f);

        __stcs(&out_mask[idx0],      p10 ? 1.f : 0.f);
        __stcs(&out_mask[idx0 + 32], p11 ? 1.f : 0.f);

        __shared__ unsigned int c[8];
        if (tid < 8) c[tid] = 0u;
        __syncthreads();

        bool pr0[4] = {p00, p10, p20, p30};
        bool pr1[4] = {p01, p11, p21, p31};
        int lane = threadIdx.x;   // TW == 32, so threadIdx.x is the lane id
        #pragma unroll
        for (int m = 0; m < 4; m++) {
            unsigned bi = __ballot_sync(0xFFFFFFFFu, t0 && pr0[m]);
            unsigned bu = __ballot_sync(0xFFFFFFFFu, t0 || pr0[m]);
            unsigned ci = __ballot_sync(0xFFFFFFFFu, t1 && pr1[m]);
            unsigned cu = __ballot_sync(0xFFFFFFFFu, t1 || pr1[m]);
            if (lane == 0) {
                atomicAdd(&c[2 * m + 0], (unsigned)(__popc(bi) + __popc(ci)));
                atomicAdd(&c[2 * m + 1], (unsigned)(__popc(bu) + __popc(cu)));
            }
        }
        __syncthreads();
        if (tid < 8)
            atomicAdd(&g_cnt[b * 8 + tid], c[tid]);
    }
}

__global__ void iou_kernel(float* __restrict__ out_ious) {
    int m = threadIdx.x;
    if (m < 4) {
        float s = 0.f;
        for (int b = 0; b < BATCH; b++) {
            float inter = (float)g_cnt[b * 8 + 2 * m + 0];
            float uni   = (float)g_cnt[b * 8 + 2 * m + 1];
            s += inter / (uni + 1e-6f);
        }
        out_ious[m] = s * (1.0f / (float)BATCH);
    }
}

// ---------------------------------------------------------------------------
extern "C" void kernel_launch(void* const* d_in, const int* in_sizes, int n_in,
                              void* d_out, int out_size) {
    const float* fm      = (const float*)d_in[0];  // (16,3,256,256)
    const float* seg     = (const float*)d_in[1];  // (16,256,256)
    const float* depth   = (const float*)d_in[2];
    const float* targets = (const float*)d_in[3];
    const float* sam     = (const float*)d_in[4];
    float* out = (float*)d_out;

    mf_init<<<(BATCH * HW + 255) / 256, 256>>>(seg);
    zero_pad<<<BATCH * NPLANE, 256>>>();
    build_kernels<<<dim3(W / TW, H / TH, BATCH), dim3(TW, TH)>>>(fm, depth);

    dim3 blk(TW, TH);
    dim3 grd(W / TILEW, H / TH, BATCH);   // (4, 32, 16) = 2048 blocks
    int src = 0;
    for (int it = 0; it < NITER; it++) {
        mf_iter<<<grd, blk>>>(src, it == NITER - 1, seg, targets, sam, out);
        src ^= 1;
    }

    iou_kernel<<<1, 32>>>(out + (out_size - 4));
}

// round 7
// speedup vs baseline: 1.2771x; 1.0122x over previous
#include <cuda_runtime.h>

#define BATCH 16
#define H 256
#define W 256
#define HW (H*W)
#define NPLANE 12            // unique off-center taps (center weight == 1)
#define RAD 2
#define NITER 10
#define GB 8                 // batches per phase (L2 working set ~68 MB)

// padded weight plane: 2 cols left, 2 cols right, 2 rows bottom (zeros)
#define PW 260
#define PH 258
#define PLANE (PW*PH)

// mf_iter tile: 32x8 threads, 2 px/thread (lx and lx+32) -> 64x8 pixels
#define TW 32
#define TH 8
#define TILEW 64
#define SHW (TILEW + 2*RAD)   // 68
#define SHH (TH + 2*RAD)      // 12

// build tile: 32x8 px
#define BHALOW (TW + 2*RAD)   // 36
#define BHALOH (TH + 2*RAD)   // 12

// Scratch (no cudaMalloc): ~137 MB of __device__ globals.
__device__ float2 g_k[BATCH * NPLANE * PLANE];  // interleaved {kA,kB}, padded (~103 MB)
__device__ float4 g_L[2][BATCH * HW];           // {logxA, log1mxA, logxB, log1mxB} ping-pong
__device__ unsigned int g_cnt[BATCH * 8];

// ---------------------------------------------------------------------------
__global__ __launch_bounds__(256) void mf_init(const float* __restrict__ seg) {
    int i = blockIdx.x * 256 + threadIdx.x;
    if (i < BATCH * HW) {
        float x = fminf(fmaxf(seg[i], 0.1f), 0.9f);
        float l1 = logf(x), l0 = logf(1.0f - x);
        g_L[0][i] = make_float4(l1, l0, l1, l0);
    }
    if (blockIdx.x == 0 && threadIdx.x < BATCH * 8)
        g_cnt[threadIdx.x] = 0u;
}

// Zero the padding borders of every weight plane (interior written by build).
__global__ __launch_bounds__(256) void zero_pad() {
    float2* p = g_k + (size_t)blockIdx.x * PLANE;
    const float2 z = make_float2(0.f, 0.f);
    for (int i = threadIdx.x; i < 2 * PW; i += 256) {
        int r = 256 + i / PW, c = i % PW;
        p[r * PW + c] = z;
    }
    for (int i = threadIdx.x; i < 256 * 4; i += 256) {
        int r = i / 4, cc = i % 4;
        int c = (cc < 2) ? cc : (256 + cc);
        p[r * PW + c] = z;
    }
}

// ---------------------------------------------------------------------------
// Build 12 unique-tap weight plane pairs per batch (mirror taps come from
// shifted reads of these planes; center tap weight is exactly 1).
// ---------------------------------------------------------------------------
__global__ __launch_bounds__(256) void build_kernels(
    const float* __restrict__ fm, const float* __restrict__ depth) {
    __shared__ float sf0[BHALOH][BHALOW];
    __shared__ float sf1[BHALOH][BHALOW];
    __shared__ float sf2[BHALOH][BHALOW];
    __shared__ float sd [BHALOH][BHALOW];

    int b   = blockIdx.z;
    int ty0 = blockIdx.y * TH;
    int tx0 = blockIdx.x * TW;
    int tid = threadIdx.y * TW + threadIdx.x;

    for (int i = tid; i < BHALOH * BHALOW; i += TH * TW) {
        int hy = i / BHALOW, hx = i % BHALOW;
        int gy = ty0 + hy - RAD, gx = tx0 + hx - RAD;
        float f0 = 0.f, f1 = 0.f, f2 = 0.f, d = 0.f;
        if (gy >= 0 && gy < H && gx >= 0 && gx < W) {
            int idx = gy * W + gx;
            f0 = fm[(b * 3 + 0) * HW + idx] + 10.f;
            f1 = fm[(b * 3 + 1) * HW + idx] + 10.f;
            f2 = fm[(b * 3 + 2) * HW + idx] + 10.f;
            d  = depth[b * HW + idx];
        }
        sf0[hy][hx] = f0; sf1[hy][hx] = f1; sf2[hy][hx] = f2; sd[hy][hx] = d;
    }
    __syncthreads();

    int ly = threadIdx.y, lx = threadIdx.x;
    int gy = ty0 + ly, gx = tx0 + lx;

    float c0 = sf0[ly + RAD][lx + RAD];
    float c1 = sf1[ly + RAD][lx + RAD];
    float c2 = sf2[ly + RAD][lx + RAD];
    float cd = sd [ly + RAD][lx + RAD];

    float2* kout = g_k + (size_t)(b * NPLANE) * PLANE + gy * PW + (gx + 2);

    #pragma unroll
    for (int t = 0; t < NPLANE; t++) {
        int kh = t / 5, kw = t % 5;
        float d0 = sf0[ly + kh][lx + kw] - c0;
        float d1 = sf1[ly + kh][lx + kw] - c1;
        float d2 = sf2[ly + kh][lx + kw] - c2;
        float s  = d0 * d0 + d1 * d1 + d2 * d2;
        float k  = expf(-(s / 0.02f));
        float dd = sd[ly + kh][lx + kw] - cd;
        float ks = k * expf(-((dd * dd) / 0.02f));
        kout[(size_t)t * PLANE] = make_float2(k, ks);
    }
}

// ---------------------------------------------------------------------------
// One mean-field iteration, both chains packed in float4, 2 px/thread:
//   S(p) = L(p) + sum_t [ w_t(p) * L(p+o_t) + w_t(p-o_t) * L(p-o_t) ]
// Weights (default cache policy; per-phase working set ~51.5 MB stays
// L2-resident across the phase's 10 iterations). L state uses streaming
// hints so it never displaces weights. Last iteration fuses finalize.
// ---------------------------------------------------------------------------
__global__ __launch_bounds__(256, 5) void mf_iter(
    int src, int last, int b0,
    const float* __restrict__ seg, const float* __restrict__ targets,
    const float* __restrict__ sam, float* __restrict__ out_mask) {
    __shared__ float4 sb[SHH][SHW];   // {logxA, log1mxA, logxB, log1mxB}

    int b   = b0 + blockIdx.z;
    int ty0 = blockIdx.y * TH;
    int tx0 = blockIdx.x * TILEW;
    int tid = threadIdx.y * TW + threadIdx.x;

    const float4* __restrict__ Ls = g_L[src];
    float4* Ld = g_L[src ^ 1];

    for (int i = tid; i < SHH * SHW; i += TH * TW) {
        int hy = i / SHW, hx = i % SHW;
        int gy = ty0 + hy - RAD, gx = tx0 + hx - RAD;
        float4 v = make_float4(0.f, 0.f, 0.f, 0.f);
        if ((unsigned)gy < H && (unsigned)gx < W)
            v = __ldcs(&Ls[b * HW + gy * W + gx]);
        sb[hy][hx] = v;
    }
    __syncthreads();

    int ly = threadIdx.y, lx = threadIdx.x;
    int gy = ty0 + ly, gx0 = tx0 + lx;       // px1 at gx0 + 32

    const float2* __restrict__ kp =
        g_k + (size_t)(b * NPLANE) * PLANE + gy * PW + (gx0 + 2);

    float S1A0 = 0.f, S0A0 = 0.f, S1B0 = 0.f, S0B0 = 0.f;
    float S1A1 = 0.f, S0A1 = 0.f, S1B1 = 0.f, S0B1 = 0.f;

    #pragma unroll
    for (int t = 0; t < NPLANE; t++) {
        const int kh = t / 5, kw = t % 5;
        const int moff = (2 - kh) * PW + (2 - kw);   // mirror weight offset
        float2 wf0 = __ldg(kp + (size_t)t * PLANE);
        float2 wf1 = __ldg(kp + (size_t)t * PLANE + 32);
        float2 wm0 = __ldg(kp + (size_t)t * PLANE + moff);
        float2 wm1 = __ldg(kp + (size_t)t * PLANE + moff + 32);

        float4 f0 = sb[ly + kh][lx + kw];
        float4 f1 = sb[ly + kh][lx + kw + 32];
        float4 m0 = sb[ly + 4 - kh][lx + 4 - kw];
        float4 m1 = sb[ly + 4 - kh][lx + 4 - kw + 32];

        S1A0 += wf0.x * f0.x + wm0.x * m0.x;
        S0A0 += wf0.x * f0.y + wm0.x * m0.y;
        S1B0 += wf0.y * f0.z + wm0.y * m0.z;
        S0B0 += wf0.y * f0.w + wm0.y * m0.w;
        S1A1 += wf1.x * f1.x + wm1.x * m1.x;
        S0A1 += wf1.x * f1.y + wm1.x * m1.y;
        S1B1 += wf1.y * f1.z + wm1.y * m1.z;
        S0B1 += wf1.y * f1.w + wm1.y * m1.w;
    }
    // center tap: weight exactly 1
    {
        float4 c0 = sb[ly + 2][lx + 2], c1 = sb[ly + 2][lx + 34];
        S1A0 += c0.x; S0A0 += c0.y; S1B0 += c0.z; S0B0 += c0.w;
        S1A1 += c1.x; S0A1 += c1.y; S1B1 += c1.z; S0B1 += c1.w;
    }

    int idx0 = b * HW + gy * W + gx0;

    float a1, a0;
    a1 = expf(S1A0); a0 = expf(S0A0);
    float xA0 = fminf(fmaxf(a1 / (1e-6f + (a0 + a1)), 0.1f), 0.9f);
    a1 = expf(S1B0); a0 = expf(S0B0);
    float xB0 = fminf(fmaxf(a1 / (1e-6f + (a0 + a1)), 0.1f), 0.9f);
    a1 = expf(S1A1); a0 = expf(S0A1);
    float xA1 = fminf(fmaxf(a1 / (1e-6f + (a0 + a1)), 0.1f), 0.9f);
    a1 = expf(S1B1); a0 = expf(S0B1);
    float xB1 = fminf(fmaxf(a1 / (1e-6f + (a0 + a1)), 0.1f), 0.9f);

    if (!last) {
        __stcs(&Ld[idx0], make_float4(logf(xA0), logf(1.0f - xA0),
                                      logf(xB0), logf(1.0f - xB0)));
        __stcs(&Ld[idx0 + 32], make_float4(logf(xA1), logf(1.0f - xA1),
                                           logf(xB1), logf(1.0f - xB1)));
    } else {
        // fused finalize: rgb_mask write + per-batch IoU counting
        bool t0 = (targets[idx0]      != 0.f);
        bool t1 = (targets[idx0 + 32] != 0.f);
        bool p00 = (seg[idx0]       > 0.5f), p01 = (seg[idx0 + 32]  > 0.5f);
        bool p10 = (xA0 > 0.5f),             p11 = (xA1 > 0.5f);
        bool p20 = (xB0 > 0.5f),             p21 = (xB1 > 0.5f);
        bool p30 = (sam[idx0] != 0.f),       p31 = (sam[idx0 + 32] != 0.f);

        __stcs(&out_mask[idx0],      p10 ? 1.f : 0.f);
        __stcs(&out_mask[idx0 + 32], p11 ? 1.f : 0.f);

        __shared__ unsigned int c[8];
        if (tid < 8) c[tid] = 0u;
        __syncthreads();

        bool pr0[4] = {p00, p10, p20, p30};
        bool pr1[4] = {p01, p11, p21, p31};
        int lane = threadIdx.x;   // TW == 32, so threadIdx.x is the lane id
        #pragma unroll
        for (int m = 0; m < 4; m++) {
            unsigned bi = __ballot_sync(0xFFFFFFFFu, t0 && pr0[m]);
            unsigned bu = __ballot_sync(0xFFFFFFFFu, t0 || pr0[m]);
            unsigned ci = __ballot_sync(0xFFFFFFFFu, t1 && pr1[m]);
            unsigned cu = __ballot_sync(0xFFFFFFFFu, t1 || pr1[m]);
            if (lane == 0) {
                atomicAdd(&c[2 * m + 0], (unsigned)(__popc(bi) + __popc(ci)));
                atomicAdd(&c[2 * m + 1], (unsigned)(__popc(bu) + __popc(cu)));
            }
        }
        __syncthreads();
        if (tid < 8)
            atomicAdd(&g_cnt[b * 8 + tid], c[tid]);
    }
}

__global__ void iou_kernel(float* __restrict__ out_ious) {
    int m = threadIdx.x;
    if (m < 4) {
        float s = 0.f;
        for (int b = 0; b < BATCH; b++) {
            float inter = (float)g_cnt[b * 8 + 2 * m + 0];
            float uni   = (float)g_cnt[b * 8 + 2 * m + 1];
            s += inter / (uni + 1e-6f);
        }
        out_ious[m] = s * (1.0f / (float)BATCH);
    }
}

// ---------------------------------------------------------------------------
extern "C" void kernel_launch(void* const* d_in, const int* in_sizes, int n_in,
                              void* d_out, int out_size) {
    const float* fm      = (const float*)d_in[0];  // (16,3,256,256)
    const float* seg     = (const float*)d_in[1];  // (16,256,256)
    const float* depth   = (const float*)d_in[2];
    const float* targets = (const float*)d_in[3];
    const float* sam     = (const float*)d_in[4];
    float* out = (float*)d_out;

    mf_init<<<(BATCH * HW + 255) / 256, 256>>>(seg);
    zero_pad<<<BATCH * NPLANE, 256>>>();
    build_kernels<<<dim3(W / TW, H / TH, BATCH), dim3(TW, TH)>>>(fm, depth);

    // Two-phase L2-blocked schedule: all 10 iterations for 8 batches at a
    // time. Per-phase working set = 51.5 MB weights + 16.5 MB streaming L
    // state, comfortably inside the 126 MB L2, so iterations 2..10 of each
    // phase read weights from L2. Grid 1024 blocks/launch (~1.4 waves).
    dim3 blk(TW, TH);
    dim3 grd(W / TILEW, H / TH, GB);   // (4, 32, 8) = 1024 blocks
    for (int g = 0; g < BATCH / GB; g++) {
        int src = 0;
        for (int it = 0; it < NITER; it++) {
            mf_iter<<<grd, blk>>>(src, it == NITER - 1, g * GB,
                                  seg, targets, sam, out);
            src ^= 1;
        }
    }

    iou_kernel<<<1, 32>>>(out + (out_size - 4));
}

// round 8
// speedup vs baseline: 1.4521x; 1.1370x over previous
#include <cuda_runtime.h>

#define BATCH 16
#define H 256
#define W 256
#define HW (H*W)
#define NPLANE 12            // unique off-center taps (center weight == 1)
#define RAD 2
#define NITER 10
#define GB 8                 // batches per phase (L2 working set ~68 MB)

// padded weight plane: 2 cols left, 2 cols right, 2 rows bottom (zeros)
#define PW 260
#define PH 258
#define PLANE (PW*PH)

// mf_iter tile: 512 threads, 1 px/thread -> 64x8 pixels
#define NT 512
#define TILEW 64
#define TH 8
#define SHW (TILEW + 2*RAD)   // 68
#define SHH (TH + 2*RAD)      // 12

// build tile: 32x8 px
#define BTW 32
#define BHALOW (BTW + 2*RAD)  // 36
#define BHALOH (TH + 2*RAD)   // 12

// Scratch (no cudaMalloc): ~137 MB of __device__ globals.
__device__ float2 g_k[BATCH * NPLANE * PLANE];  // interleaved {kA,kB}, padded (~103 MB)
__device__ float4 g_L[2][BATCH * HW];           // {logxA, log1mxA, logxB, log1mxB} ping-pong
__device__ unsigned int g_cnt[BATCH * 8];

// ---------------------------------------------------------------------------
__global__ __launch_bounds__(256) void mf_init(const float* __restrict__ seg) {
    int i = blockIdx.x * 256 + threadIdx.x;
    if (i < BATCH * HW) {
        float x = fminf(fmaxf(seg[i], 0.1f), 0.9f);
        float l1 = logf(x), l0 = logf(1.0f - x);
        g_L[0][i] = make_float4(l1, l0, l1, l0);
    }
    if (blockIdx.x == 0 && threadIdx.x < BATCH * 8)
        g_cnt[threadIdx.x] = 0u;
}

// Zero the padding borders of every weight plane (interior written by build).
__global__ __launch_bounds__(256) void zero_pad() {
    float2* p = g_k + (size_t)blockIdx.x * PLANE;
    const float2 z = make_float2(0.f, 0.f);
    for (int i = threadIdx.x; i < 2 * PW; i += 256) {
        int r = 256 + i / PW, c = i % PW;
        p[r * PW + c] = z;
    }
    for (int i = threadIdx.x; i < 256 * 4; i += 256) {
        int r = i / 4, cc = i % 4;
        int c = (cc < 2) ? cc : (256 + cc);
        p[r * PW + c] = z;
    }
}

// ---------------------------------------------------------------------------
// Build 12 unique-tap weight plane pairs per batch (mirror taps come from
// shifted reads of these planes; center tap weight is exactly 1).
// ---------------------------------------------------------------------------
__global__ __launch_bounds__(256) void build_kernels(
    const float* __restrict__ fm, const float* __restrict__ depth) {
    __shared__ float sf0[BHALOH][BHALOW];
    __shared__ float sf1[BHALOH][BHALOW];
    __shared__ float sf2[BHALOH][BHALOW];
    __shared__ float sd [BHALOH][BHALOW];

    int b   = blockIdx.z;
    int ty0 = blockIdx.y * TH;
    int tx0 = blockIdx.x * BTW;
    int tid = threadIdx.y * BTW + threadIdx.x;

    for (int i = tid; i < BHALOH * BHALOW; i += TH * BTW) {
        int hy = i / BHALOW, hx = i % BHALOW;
        int gy = ty0 + hy - RAD, gx = tx0 + hx - RAD;
        float f0 = 0.f, f1 = 0.f, f2 = 0.f, d = 0.f;
        if (gy >= 0 && gy < H && gx >= 0 && gx < W) {
            int idx = gy * W + gx;
            f0 = fm[(b * 3 + 0) * HW + idx] + 10.f;
            f1 = fm[(b * 3 + 1) * HW + idx] + 10.f;
            f2 = fm[(b * 3 + 2) * HW + idx] + 10.f;
            d  = depth[b * HW + idx];
        }
        sf0[hy][hx] = f0; sf1[hy][hx] = f1; sf2[hy][hx] = f2; sd[hy][hx] = d;
    }
    __syncthreads();

    int ly = threadIdx.y, lx = threadIdx.x;
    int gy = ty0 + ly, gx = tx0 + lx;

    float c0 = sf0[ly + RAD][lx + RAD];
    float c1 = sf1[ly + RAD][lx + RAD];
    float c2 = sf2[ly + RAD][lx + RAD];
    float cd = sd [ly + RAD][lx + RAD];

    float2* kout = g_k + (size_t)(b * NPLANE) * PLANE + gy * PW + (gx + 2);

    #pragma unroll
    for (int t = 0; t < NPLANE; t++) {
        int kh = t / 5, kw = t % 5;
        float d0 = sf0[ly + kh][lx + kw] - c0;
        float d1 = sf1[ly + kh][lx + kw] - c1;
        float d2 = sf2[ly + kh][lx + kw] - c2;
        float s  = d0 * d0 + d1 * d1 + d2 * d2;
        float k  = expf(-(s / 0.02f));
        float dd = sd[ly + kh][lx + kw] - cd;
        float ks = k * expf(-((dd * dd) / 0.02f));
        kout[(size_t)t * PLANE] = make_float2(k, ks);
    }
}

// ---------------------------------------------------------------------------
// One mean-field iteration, both chains packed in float4, 1 px/thread,
// 512-thread blocks (<=32 regs -> 4 blocks/SM = 100% theoretical occupancy):
//   S(p) = L(p) + sum_t [ w_t(p) * L(p+o_t) + w_t(p-o_t) * L(p-o_t) ]
// Weights default-policy (phase working set ~51.5 MB L2-resident);
// L state streaming. Last iteration fuses mask write + IoU counting.
// ---------------------------------------------------------------------------
__global__ __launch_bounds__(NT, 4) void mf_iter(
    int src, int last, int b0,
    const float* __restrict__ seg, const float* __restrict__ targets,
    const float* __restrict__ sam, float* __restrict__ out_mask) {
    __shared__ float4 sb[SHH][SHW];   // {logxA, log1mxA, logxB, log1mxB}

    int b   = b0 + blockIdx.z;
    int ty0 = blockIdx.y * TH;
    int tx0 = blockIdx.x * TILEW;
    int tid = threadIdx.x;

    const float4* __restrict__ Ls = g_L[src];
    float4* Ld = g_L[src ^ 1];

    #pragma unroll
    for (int i = tid; i < SHH * SHW; i += NT) {
        int hy = i / SHW, hx = i % SHW;
        int gy = ty0 + hy - RAD, gx = tx0 + hx - RAD;
        float4 v = make_float4(0.f, 0.f, 0.f, 0.f);
        if ((unsigned)gy < H && (unsigned)gx < W)
            v = __ldcs(&Ls[b * HW + gy * W + gx]);
        sb[hy][hx] = v;
    }
    __syncthreads();

    int lx = tid & (TILEW - 1);       // 0..63, lanes consecutive in x
    int ly = tid >> 6;                // 0..7
    int gy = ty0 + ly, gx = tx0 + lx;

    const float2* __restrict__ kp =
        g_k + (size_t)(b * NPLANE) * PLANE + gy * PW + (gx + 2);

    float S1A = 0.f, S0A = 0.f, S1B = 0.f, S0B = 0.f;

    #pragma unroll
    for (int t = 0; t < NPLANE; t++) {
        const int kh = t / 5, kw = t % 5;
        const int moff = (2 - kh) * PW + (2 - kw);   // mirror weight offset
        float2 wf = __ldg(kp + (size_t)t * PLANE);
        float2 wm = __ldg(kp + (size_t)t * PLANE + moff);

        float4 f = sb[ly + kh][lx + kw];
        float4 m = sb[ly + 4 - kh][lx + 4 - kw];

        S1A += wf.x * f.x + wm.x * m.x;
        S0A += wf.x * f.y + wm.x * m.y;
        S1B += wf.y * f.z + wm.y * m.z;
        S0B += wf.y * f.w + wm.y * m.w;
    }
    // center tap: weight exactly 1
    {
        float4 c = sb[ly + 2][lx + 2];
        S1A += c.x; S0A += c.y; S1B += c.z; S0B += c.w;
    }

    int idx = b * HW + gy * W + gx;

    float a1, a0;
    a1 = expf(S1A); a0 = expf(S0A);
    float xA = fminf(fmaxf(a1 / (1e-6f + (a0 + a1)), 0.1f), 0.9f);
    a1 = expf(S1B); a0 = expf(S0B);
    float xB = fminf(fmaxf(a1 / (1e-6f + (a0 + a1)), 0.1f), 0.9f);

    if (!last) {
        __stcs(&Ld[idx], make_float4(logf(xA), logf(1.0f - xA),
                                     logf(xB), logf(1.0f - xB)));
    } else {
        // fused finalize: rgb_mask write + per-batch IoU counting
        bool t0 = (targets[idx] != 0.f);
        bool p0 = (seg[idx]  > 0.5f);
        bool p1 = (xA > 0.5f);
        bool p2 = (xB > 0.5f);
        bool p3 = (sam[idx] != 0.f);

        __stcs(&out_mask[idx], p1 ? 1.f : 0.f);

        __shared__ unsigned int c[8];
        if (tid < 8) c[tid] = 0u;
        __syncthreads();

        bool pr[4] = {p0, p1, p2, p3};
        int lane = tid & 31;
        #pragma unroll
        for (int m = 0; m < 4; m++) {
            unsigned bi = __ballot_sync(0xFFFFFFFFu, t0 && pr[m]);
            unsigned bu = __ballot_sync(0xFFFFFFFFu, t0 || pr[m]);
            if (lane == 0) {
                atomicAdd(&c[2 * m + 0], (unsigned)__popc(bi));
                atomicAdd(&c[2 * m + 1], (unsigned)__popc(bu));
            }
        }
        __syncthreads();
        if (tid < 8)
            atomicAdd(&g_cnt[b * 8 + tid], c[tid]);
    }
}

__global__ void iou_kernel(float* __restrict__ out_ious) {
    int m = threadIdx.x;
    if (m < 4) {
        float s = 0.f;
        for (int b = 0; b < BATCH; b++) {
            float inter = (float)g_cnt[b * 8 + 2 * m + 0];
            float uni   = (float)g_cnt[b * 8 + 2 * m + 1];
            s += inter / (uni + 1e-6f);
        }
        out_ious[m] = s * (1.0f / (float)BATCH);
    }
}

// ---------------------------------------------------------------------------
extern "C" void kernel_launch(void* const* d_in, const int* in_sizes, int n_in,
                              void* d_out, int out_size) {
    const float* fm      = (const float*)d_in[0];  // (16,3,256,256)
    const float* seg     = (const float*)d_in[1];  // (16,256,256)
    const float* depth   = (const float*)d_in[2];
    const float* targets = (const float*)d_in[3];
    const float* sam     = (const float*)d_in[4];
    float* out = (float*)d_out;

    mf_init<<<(BATCH * HW + 255) / 256, 256>>>(seg);
    zero_pad<<<BATCH * NPLANE, 256>>>();
    build_kernels<<<dim3(W / BTW, H / TH, BATCH), dim3(BTW, TH)>>>(fm, depth);

    // Two-phase L2-blocked schedule (8 batches x 10 iterations per phase).
    dim3 grd(W / TILEW, H / TH, GB);   // (4, 32, 8) = 1024 blocks
    for (int g = 0; g < BATCH / GB; g++) {
        int src = 0;
        for (int it = 0; it < NITER; it++) {
            mf_iter<<<grd, NT>>>(src, it == NITER - 1, g * GB,
                                 seg, targets, sam, out);
            src ^= 1;
        }
    }

    iou_kernel<<<1, 32>>>(out + (out_size - 4));
}